// round 1
// baseline (speedup 1.0000x reference)
#include <cuda_runtime.h>
#include <cuda_bf16.h>

#define NN 100000
#define NE 1600000
#define D  128
#define NL 3

// ---- scratch (static device globals; no runtime allocation) ----
__device__ int   g_deg[NN];
__device__ float g_inv[NN];
__device__ int   g_rowptr[NN + 1];
__device__ int   g_cursor[NN];
__device__ int   g_esrc[NE];
__device__ float g_x[NN * D];      // layer ping
__device__ float g_y[NN * D];      // layer pong
__device__ float g_neigh[NN * D];  // mean-aggregated neighbor features

// ---------------------------------------------------------------
__global__ void k_zero_deg() {
    int i = blockIdx.x * blockDim.x + threadIdx.x;
    if (i < NN) g_deg[i] = 0;
}

__global__ void k_count(const int* __restrict__ dst) {
    int e = blockIdx.x * blockDim.x + threadIdx.x;
    if (e < NE) atomicAdd(&g_deg[dst[e]], 1);
}

// Single-block exclusive scan over g_deg -> g_rowptr; also inv-deg + cursor init.
__global__ void k_scan() {
    __shared__ int part[1024];
    int t = threadIdx.x;
    const int C = (NN + 1023) / 1024;  // 98
    int beg = t * C;
    int end = min(beg + C, NN);
    int s = 0;
    for (int i = beg; i < end; i++) s += g_deg[i];
    part[t] = s;
    __syncthreads();
    // Hillis-Steele inclusive scan
    for (int off = 1; off < 1024; off <<= 1) {
        int v = (t >= off) ? part[t - off] : 0;
        __syncthreads();
        if (t >= off) part[t] += v;
        __syncthreads();
    }
    int run = (t == 0) ? 0 : part[t - 1];
    for (int i = beg; i < end; i++) {
        int d = g_deg[i];
        g_rowptr[i] = run;
        g_cursor[i] = run;
        g_inv[i]    = 1.0f / (float)max(d, 1);
        run += d;
    }
    if (t == 1023) g_rowptr[NN] = part[1023];
}

__global__ void k_fill(const int* __restrict__ src, const int* __restrict__ dst) {
    int e = blockIdx.x * blockDim.x + threadIdx.x;
    if (e < NE) {
        int p = atomicAdd(&g_cursor[dst[e]], 1);
        g_esrc[p] = src[e];
    }
}

// One warp per destination node. lane holds one float4 (128 floats across warp).
__global__ void k_agg(const float4* __restrict__ xin) {
    int w    = (blockIdx.x * blockDim.x + threadIdx.x) >> 5;
    int lane = threadIdx.x & 31;
    if (w >= NN) return;
    int beg = g_rowptr[w];
    int end = g_rowptr[w + 1];
    float4 a0 = make_float4(0.f, 0.f, 0.f, 0.f);
    float4 a1 = make_float4(0.f, 0.f, 0.f, 0.f);
    int e = beg;
    for (; e + 1 < end; e += 2) {  // 2-way unroll for MLP
        int s0 = g_esrc[e];
        int s1 = g_esrc[e + 1];
        float4 v0 = __ldg(xin + (long)s0 * 32 + lane);
        float4 v1 = __ldg(xin + (long)s1 * 32 + lane);
        a0.x += v0.x; a0.y += v0.y; a0.z += v0.z; a0.w += v0.w;
        a1.x += v1.x; a1.y += v1.y; a1.z += v1.z; a1.w += v1.w;
    }
    if (e < end) {
        int s0 = g_esrc[e];
        float4 v0 = __ldg(xin + (long)s0 * 32 + lane);
        a0.x += v0.x; a0.y += v0.y; a0.z += v0.z; a0.w += v0.w;
    }
    float iv = g_inv[w];
    float4 r;
    r.x = (a0.x + a1.x) * iv;
    r.y = (a0.y + a1.y) * iv;
    r.z = (a0.z + a1.z) * iv;
    r.w = (a0.w + a1.w) * iv;
    ((float4*)g_neigh)[(long)w * 32 + lane] = r;
}

// out[r][c] = relu?( x[r]@Ws + neigh[r]@Wn + b )
// Block: 256 threads, 64 rows x 128 cols. K=256 (x||neigh), chunked by 32.
// Thread (rg,cg): rows rg*4..+3, cols cg*8..+7 -> 32 fp32 accumulators.
__global__ void __launch_bounds__(256) k_gemm(
    const float* __restrict__ xin, float* __restrict__ out,
    const float* __restrict__ Wself, const float* __restrict__ Wneigh,
    const float* __restrict__ bias, int layer, int do_relu)
{
    __shared__ float Wt[32][128];   // 16 KB
    __shared__ float Xs[64][33];    // 8.25 KB, +1 pad -> conflict-free

    int t  = threadIdx.x;
    int cg = t & 15;       // 0..15
    int rg = t >> 4;       // 0..15
    int c0 = cg * 8;
    int r0 = rg * 4;
    int rowBase = blockIdx.x * 64;

    float acc[4][8];
#pragma unroll
    for (int i = 0; i < 4; i++)
#pragma unroll
        for (int j = 0; j < 8; j++) acc[i][j] = 0.f;

    const float* Wl_s = Wself  + (long)layer * D * D;
    const float* Wl_n = Wneigh + (long)layer * D * D;

    for (int kc = 0; kc < 8; kc++) {
        int kb = kc * 32;  // global k base in concat(x, neigh)
        const float* Wsrc = (kb < D) ? Wl_s : Wl_n;
        const float* Xsrc = (kb < D) ? xin  : g_neigh;
        int koff = (kb < D) ? kb : (kb - D);

        // load W chunk [32][128]: 1024 float4, 4 per thread (flat copy)
        {
            const float4* s4 = (const float4*)(Wsrc + (long)koff * D);
            float4* d4 = (float4*)&Wt[0][0];
#pragma unroll
            for (int i = t; i < 32 * 32; i += 256) d4[i] = s4[i];
        }
        // load X chunk [64 rows][32 k]: 512 float4, 2 per thread
        {
#pragma unroll
            for (int i = t; i < 64 * 8; i += 256) {
                int r = i >> 3, q = i & 7;
                int row = rowBase + r;
                float4 v = make_float4(0.f, 0.f, 0.f, 0.f);
                if (row < NN)
                    v = *(const float4*)(Xsrc + (long)row * D + koff + q * 4);
                Xs[r][q * 4 + 0] = v.x;
                Xs[r][q * 4 + 1] = v.y;
                Xs[r][q * 4 + 2] = v.z;
                Xs[r][q * 4 + 3] = v.w;
            }
        }
        __syncthreads();

#pragma unroll
        for (int kk = 0; kk < 32; kk++) {
            float4 w0 = *(const float4*)(&Wt[kk][c0]);
            float4 w1 = *(const float4*)(&Wt[kk][c0 + 4]);
#pragma unroll
            for (int i = 0; i < 4; i++) {
                float xv = Xs[r0 + i][kk];
                acc[i][0] = fmaf(xv, w0.x, acc[i][0]);
                acc[i][1] = fmaf(xv, w0.y, acc[i][1]);
                acc[i][2] = fmaf(xv, w0.z, acc[i][2]);
                acc[i][3] = fmaf(xv, w0.w, acc[i][3]);
                acc[i][4] = fmaf(xv, w1.x, acc[i][4]);
                acc[i][5] = fmaf(xv, w1.y, acc[i][5]);
                acc[i][6] = fmaf(xv, w1.z, acc[i][6]);
                acc[i][7] = fmaf(xv, w1.w, acc[i][7]);
            }
        }
        __syncthreads();
    }

    // epilogue: bias (+relu), vectorized store
    const float* bl = bias + (long)layer * D;
    float bv[8];
#pragma unroll
    for (int j = 0; j < 8; j++) bv[j] = bl[c0 + j];

#pragma unroll
    for (int i = 0; i < 4; i++) {
        int row = rowBase + r0 + i;
        if (row >= NN) continue;
        float o[8];
#pragma unroll
        for (int j = 0; j < 8; j++) {
            float v = acc[i][j] + bv[j];
            o[j] = do_relu ? fmaxf(v, 0.f) : v;
        }
        float4 o0 = make_float4(o[0], o[1], o[2], o[3]);
        float4 o1 = make_float4(o[4], o[5], o[6], o[7]);
        *(float4*)(out + (long)row * D + c0)     = o0;
        *(float4*)(out + (long)row * D + c0 + 4) = o1;
    }
}

// ---------------------------------------------------------------
extern "C" void kernel_launch(void* const* d_in, const int* in_sizes, int n_in,
                              void* d_out, int out_size) {
    const float* emb = (const float*)d_in[0];
    const float* Ws  = (const float*)d_in[1];
    const float* Wn  = (const float*)d_in[2];
    const float* b   = (const float*)d_in[3];
    const int*   src = (const int*)d_in[4];
    const int*   dst = (const int*)d_in[5];
    float*       out = (float*)d_out;

    void *px, *py;
    cudaGetSymbolAddress(&px, g_x);
    cudaGetSymbolAddress(&py, g_y);
    float* xbuf = (float*)px;
    float* ybuf = (float*)py;

    // CSR build (once per launch)
    k_zero_deg<<<(NN + 255) / 256, 256>>>();
    k_count<<<(NE + 255) / 256, 256>>>(dst);
    k_scan<<<1, 1024>>>();
    k_fill<<<(NE + 255) / 256, 256>>>(src, dst);

    const int aggGrid  = (NN + 7) / 8;    // 8 warps per 256-thread block
    const int gemmGrid = (NN + 63) / 64;

    // layer 0: emb -> g_x   (relu)
    k_agg<<<aggGrid, 256>>>((const float4*)emb);
    k_gemm<<<gemmGrid, 256>>>(emb, xbuf, Ws, Wn, b, 0, 1);

    // layer 1: g_x -> g_y   (relu)
    k_agg<<<aggGrid, 256>>>((const float4*)xbuf);
    k_gemm<<<gemmGrid, 256>>>(xbuf, ybuf, Ws, Wn, b, 1, 1);

    // layer 2: g_y -> d_out (no relu)
    k_agg<<<aggGrid, 256>>>((const float4*)ybuf);
    k_gemm<<<gemmGrid, 256>>>(ybuf, out, Ws, Wn, b, 2, 0);
}